// round 10
// baseline (speedup 1.0000x reference)
#include <cuda_runtime.h>
#include <cuda_bf16.h>

#define B      512
#define DIM    128
#define MARGIN 0.2f
#define EPSF   1e-6f
#define BIGF   1e30f
#define SENTTH 1e29f
#define FULLM  0xffffffffu

#define LDJ 132   // Fj/u row stride (floats); quarter-warp conflict-free LDS.128
#define LDD 516   // D slab row stride (floats)
#define NT  512   // threads per block

// Accumulators (allocation-free rule). Statics init to zero; the last block
// resets them after use, so every graph replay starts from zero.
__device__ double g_num = 0.0;
__device__ unsigned long long g_den = 0ull;
__device__ unsigned int g_done = 0u;

static __device__ __forceinline__ unsigned smem_addr(const void* p) {
    return (unsigned)__cvta_generic_to_shared(p);
}

// ---------------------------------------------------------------------------
// ONE fused kernel, 512 threads. Block b = anchor rows [4b, 4b+4).
// Phase A: 4 j-tiles of 128, double-buffered cp.async staging (tile p+2
//   prefetched while tile p computes). Thread (q = tid/128, jl = tid%128)
//   computes the quarter-dot over d in [32q, 32q+32) for column jl; quarters
//   combine via float4 smem partials; q==0 writes D row slab.
// Phase B (warps 0-3): register-resident bitonic sort per row (verified R6),
//   LSB tag + closed-form prefix, single atomic finalize.
// ---------------------------------------------------------------------------
__global__ __launch_bounds__(NT) void fused_kernel(const float* __restrict__ F,
                                                   const int* __restrict__ mask,
                                                   float* __restrict__ out) {
    extern __shared__ float sm[];
    float*  u_s  = sm;                         //   4 * 132
    float*  Fj_s = u_s + 4 * LDJ;              // 2 buffers * 128 * 132
    float*  D_s  = Fj_s + 2 * 128 * LDJ;       //   4 * 516
    float*  s_ni = D_s + 4 * LDD;              //   4
    float4* s_p4 = (float4*)(s_ni + 4);        // 3 * 128 float4
    float*  s_pn = (float*)(s_p4 + 3 * 128);   // 3 * 128
    float*  s_bs = s_pn + 3 * 128;             //   4
    unsigned long long* s_bd = (unsigned long long*)(s_bs + 4);   // 4

    const int tid  = threadIdx.x;
    const int lane = tid & 31;
    const int warp = tid >> 5;
    const int i0   = blockIdx.x * 4;
    const int q    = tid >> 7;        // d-quarter (uniform per warp)
    const int jl   = tid & 127;       // j column within tile

    // ---- prefetch mask row for my sort row (warps 0-3) ----------------------
    int4 m4p[4];
    if (warp < 4) {
        const int4* Mrow = (const int4*)(mask + (i0 + warp) * B);
#pragma unroll
        for (int qq = 0; qq < 4; qq++) m4p[qq] = Mrow[lane * 4 + qq];
    }

    // ---- stage u = f(anchor rows) + eps (1 element per thread) --------------
    {
        const int r = tid >> 7, d = tid & 127;
        u_s[r * LDJ + d] = F[(i0 + r) * DIM + d] + EPSF;
    }

    // ---- issue async staging for tiles 0 and 1 ------------------------------
#define CP_ISSUE_TILE(P, BUF)                                                  \
    {                                                                          \
        _Pragma("unroll")                                                      \
        for (int k = 0; k < 8; k++) {                                          \
            const int idx = tid + (k << 9);                                    \
            const int r = idx >> 5, c = idx & 31;                              \
            const unsigned dst = smem_addr(&Fj_s[(BUF) * 128 * LDJ + r * LDJ + 4 * c]); \
            const float* src = F + (128 * (P) + r) * DIM + 4 * c;              \
            asm volatile("cp.async.cg.shared.global [%0], [%1], 16;"           \
                         :: "r"(dst), "l"(src));                               \
        }                                                                      \
        asm volatile("cp.async.commit_group;");                                \
    }

    CP_ISSUE_TILE(0, 0)
    CP_ISSUE_TILE(1, 1)

    __syncthreads();   // u_s visible

    // ---- |u_i|^2 (warps 0-3; warp w -> row w) --------------------------------
    if (warp < 4) {
        float s = 0.f;
#pragma unroll
        for (int qq = 0; qq < 4; qq++) {
            const float x = u_s[warp * LDJ + lane + 32 * qq];
            s = fmaf(x, x, s);
        }
#pragma unroll
        for (int off = 16; off; off >>= 1) s += __shfl_down_sync(FULLM, s, off);
        if (lane == 0) s_ni[warp] = s;
    }

    const float4* U0 = (const float4*)&u_s[0 * LDJ + 32 * q];
    const float4* U1 = (const float4*)&u_s[1 * LDJ + 32 * q];
    const float4* U2 = (const float4*)&u_s[2 * LDJ + 32 * q];
    const float4* U3 = (const float4*)&u_s[3 * LDJ + 32 * q];

#define DO_TILE(P, WAITN, PREFETCH)                                            \
    {                                                                          \
        asm volatile("cp.async.wait_group %0;" :: "n"(WAITN));                 \
        __syncthreads();  /* tile P resident for all threads */                \
        const int buf = (P) & 1;                                               \
        float a0 = 0.f, a1 = 0.f, a2 = 0.f, a3 = 0.f, nf = 0.f;                \
        const float4* fj = (const float4*)&Fj_s[buf * 128 * LDJ + jl * LDJ + 32 * q]; \
        _Pragma("unroll")                                                      \
        for (int dq = 0; dq < 8; dq++) {                                       \
            const float4 fv = fj[dq];                                          \
            nf = fmaf(fv.x, fv.x, fmaf(fv.y, fv.y,                             \
                 fmaf(fv.z, fv.z, fmaf(fv.w, fv.w, nf))));                     \
            const float4 ua = U0[dq];                                          \
            a0 = fmaf(ua.x, fv.x, fmaf(ua.y, fv.y,                             \
                 fmaf(ua.z, fv.z, fmaf(ua.w, fv.w, a0))));                     \
            const float4 ub = U1[dq];                                          \
            a1 = fmaf(ub.x, fv.x, fmaf(ub.y, fv.y,                             \
                 fmaf(ub.z, fv.z, fmaf(ub.w, fv.w, a1))));                     \
            const float4 uc = U2[dq];                                          \
            a2 = fmaf(uc.x, fv.x, fmaf(uc.y, fv.y,                             \
                 fmaf(uc.z, fv.z, fmaf(uc.w, fv.w, a2))));                     \
            const float4 ud = U3[dq];                                          \
            a3 = fmaf(ud.x, fv.x, fmaf(ud.y, fv.y,                             \
                 fmaf(ud.z, fv.z, fmaf(ud.w, fv.w, a3))));                     \
        }                                                                      \
        if (q != 0) {                                                          \
            s_p4[(q - 1) * 128 + jl] = make_float4(a0, a1, a2, a3);            \
            s_pn[(q - 1) * 128 + jl] = nf;                                     \
        }                                                                      \
        __syncthreads();  /* partials visible; buffer reads complete */        \
        if (q == 0) {                                                          \
            const float4 p1 = s_p4[jl], p2 = s_p4[128 + jl], p3 = s_p4[256 + jl]; \
            const float NF = nf + s_pn[jl] + s_pn[128 + jl] + s_pn[256 + jl];  \
            const float A0 = a0 + p1.x + p2.x + p3.x;                          \
            const float A1 = a1 + p1.y + p2.y + p3.y;                          \
            const float A2 = a2 + p1.z + p2.z + p3.z;                          \
            const float A3 = a3 + p1.w + p2.w + p3.w;                          \
            const int jc = (P) * 128 + jl;                                     \
            D_s[0 * LDD + jc] = sqrtf(fmaxf(s_ni[0] + NF - 2.f * A0, 0.f));    \
            D_s[1 * LDD + jc] = sqrtf(fmaxf(s_ni[1] + NF - 2.f * A1, 0.f));    \
            D_s[2 * LDD + jc] = sqrtf(fmaxf(s_ni[2] + NF - 2.f * A2, 0.f));    \
            D_s[3 * LDD + jc] = sqrtf(fmaxf(s_ni[3] + NF - 2.f * A3, 0.f));    \
        }                                                                      \
        if (PREFETCH) CP_ISSUE_TILE((P) + 2, (P) & 1)                          \
    }

    DO_TILE(0, 1, 1)
    DO_TILE(1, 1, 1)
    DO_TILE(2, 1, 0)
    DO_TILE(3, 0, 0)

    __syncthreads();   // D_s complete

    // =========================================================================
    // Phase B (warps 0-3): register-resident sort of row i0+warp.
    // Element e = lane*16 + r. LSB tag: pos=(d+margin)|1, neg=d&~1,
    // excluded diagonal = BIGF (value-guarded out of float sums).
    // =========================================================================
    if (warp < 4) {
        const int i = i0 + warp;
        float v[16];
        int npos = 0, nneg = 0;

#pragma unroll
        for (int qq = 0; qq < 4; qq++) {
            const float4 d4 = *(const float4*)&D_s[warp * LDD + lane * 16 + 4 * qq];
            const float dv[4] = {d4.x, d4.y, d4.z, d4.w};
            const int   mv[4] = {m4p[qq].x, m4p[qq].y, m4p[qq].z, m4p[qq].w};
#pragma unroll
            for (int t = 0; t < 4; t++) {
                const int j = lane * 16 + qq * 4 + t;
                unsigned kb;
                if (mv[t] != 0) {
                    kb = __float_as_uint(dv[t] + MARGIN) | 1u;
                    npos++;
                } else if (j == i) {
                    kb = __float_as_uint(BIGF) & ~1u;
                } else {
                    kb = __float_as_uint(dv[t]) & ~1u;
                    nneg++;
                }
                v[qq * 4 + t] = __uint_as_float(kb);
            }
        }
        const int np = __reduce_add_sync(FULLM, npos);
        const int nn = __reduce_add_sync(FULLM, nneg);

        // bitonic sort of 512 keys, ascending (register + shfl only)
#pragma unroll
        for (int k = 2; k <= 512; k <<= 1) {
            const bool asc_lane_valid = (k >= 16);
            const bool asc_l = ((lane & (k >> 4)) == 0);
#pragma unroll
            for (int j = k >> 1; j >= 1; j >>= 1) {
                if (j >= 16) {
                    const int jl2 = j >> 4;
                    const bool keep_min = (((lane & jl2) == 0) == asc_l);
#pragma unroll
                    for (int r = 0; r < 16; r++) {
                        const float pv = __shfl_xor_sync(FULLM, v[r], jl2);
                        v[r] = keep_min ? fminf(v[r], pv) : fmaxf(v[r], pv);
                    }
                } else {
#pragma unroll
                    for (int r = 0; r < 16; r++) {
                        if ((r & j) == 0) {
                            const int r2 = r | j;
                            const bool asc = asc_lane_valid ? asc_l : ((r & k) == 0);
                            const float a = v[r], bb = v[r2];
                            const float lo = fminf(a, bb), hi = fmaxf(a, bb);
                            v[r]  = asc ? lo : hi;
                            v[r2] = asc ? hi : lo;
                        }
                    }
                }
            }
        }

        // pass 1: per-lane negative (sum, count), sentinel value-guarded
        float runs = 0.f;
        int   runc = 0;
#pragma unroll
        for (int r = 0; r < 16; r++) {
            const bool isneg = ((__float_as_uint(v[r]) & 1u) == 0) && (v[r] < SENTTH);
            if (isneg) { runs += v[r]; runc++; }
        }
        float ls = runs;
        int   lc = runc;
#pragma unroll
        for (int off = 1; off < 32; off <<= 1) {
            const float y = __shfl_up_sync(FULLM, ls, off);
            const int   z = __shfl_up_sync(FULLM, lc, off);
            if (lane >= off) { ls += y; lc += z; }
        }
        float rs = ls - runs;
        int   rc = lc - runc;

        // pass 2: positive contributions
        float local = 0.f;
#pragma unroll
        for (int r = 0; r < 16; r++) {
            const bool ispos = (__float_as_uint(v[r]) & 1u) != 0;
            if (ispos) {
                local += (float)rc * v[r] - rs;
            } else if (v[r] < SENTTH) {
                rs += v[r];
                rc++;
            }
        }

#pragma unroll
        for (int off = 16; off; off >>= 1)
            local += __shfl_down_sync(FULLM, local, off);

        if (lane == 0) {
            s_bs[warp] = local;
            s_bd[warp] = (unsigned long long)np * (unsigned long long)nn;
        }
    }
    __syncthreads();

    if (tid == 0) {
        const float s = s_bs[0] + s_bs[1] + s_bs[2] + s_bs[3];
        const unsigned long long d = s_bd[0] + s_bd[1] + s_bd[2] + s_bd[3];
        atomicAdd(&g_num, (double)s);
        atomicAdd(&g_den, d);
        __threadfence();
        const unsigned int ticket = atomicAdd(&g_done, 1u);
        if (ticket == gridDim.x - 1) {
            const double num = atomicAdd(&g_num, 0.0);
            const unsigned long long den = atomicAdd(&g_den, 0ull);
            out[0] = (den > 0ull) ? (float)(num / (double)den) : 0.0f;
            g_num  = 0.0;
            g_den  = 0ull;
            __threadfence();
            g_done = 0u;
        }
    }
}

// ---------------------------------------------------------------------------
extern "C" void kernel_launch(void* const* d_in, const int* in_sizes, int n_in,
                              void* d_out, int out_size) {
    const float* features = (const float*)d_in[0];   // [512,128] f32
    const int*   mask     = (const int*)d_in[1];     // [512,512] i32
    float* out = (float*)d_out;

    const int smem_bytes =
        (4 * LDJ + 2 * 128 * LDJ + 4 * LDD + 4 + 3 * 128 * 4 + 3 * 128 + 4)
            * (int)sizeof(float)
        + 4 * (int)sizeof(unsigned long long);
    static bool attr_set = false;
    if (!attr_set) {
        cudaFuncSetAttribute(fused_kernel, cudaFuncAttributeMaxDynamicSharedMemorySize,
                             smem_bytes);
        attr_set = true;
    }

    fused_kernel<<<B / 4, NT, smem_bytes>>>(features, mask, out);
}

// round 11
// speedup vs baseline: 1.0153x; 1.0153x over previous
#include <cuda_runtime.h>
#include <cuda_bf16.h>

#define B      512
#define DIM    128
#define MARGIN 0.2f
#define EPSF   1e-6f
#define BIGF   1e30f
#define SENTTH 1e29f
#define FULLM  0xffffffffu

#define LDJ 132   // Fj/u row stride (floats); quarter-warp conflict-free LDS.128
#define LDD 516   // D slab row stride (floats)
#define TJ  256   // j-tile size (2 tiles cover B=512)
#define NT  1024  // threads per block (32 warps, 8 per SMSP)

// Accumulators (allocation-free rule). Statics init to zero; the last block
// resets them after use, so every graph replay starts from zero.
__device__ double g_num = 0.0;
__device__ unsigned long long g_den = 0ull;
__device__ unsigned int g_done = 0u;

// ---------------------------------------------------------------------------
// ONE fused kernel, 1024 threads (32 warps). Block b = anchor rows [4b, 4b+4).
// Phase A: 4x512 distance slab via norm expansion, 2 j-tiles of 256.
//   Thread (q = tid/256, jl = tid%256) computes the QUARTER-dot over
//   d in [32q, 32q+32) for j-column jl; quarters combine via smem partials.
// Phase B (warps 0-3): register-resident bitonic sort per row (R6-verified),
//   LSB tag + closed-form prefix, single atomic finalize.
// ---------------------------------------------------------------------------
__global__ __launch_bounds__(NT) void fused_kernel(const float* __restrict__ F,
                                                   const int* __restrict__ mask,
                                                   float* __restrict__ out) {
    extern __shared__ float sm[];
    float*  u_s  = sm;                          //   4 * 132
    float*  Fj_s = u_s + 4 * LDJ;               // 256 * 132
    float*  D_s  = Fj_s + TJ * LDJ;             //   4 * 516
    float*  s_ni = D_s + 4 * LDD;               //   4
    float4* s_p4 = (float4*)(s_ni + 4);         // 3 * 256 float4
    float*  s_pn = (float*)(s_p4 + 3 * 256);    // 3 * 256
    float*  s_bs = s_pn + 3 * 256;              //   4
    unsigned long long* s_bd = (unsigned long long*)(s_bs + 4);   // 4

    const int tid  = threadIdx.x;
    const int lane = tid & 31;
    const int warp = tid >> 5;
    const int i0   = blockIdx.x * 4;
    const int q    = tid >> 8;        // d-quarter (uniform per warp)
    const int jl   = tid & 255;       // j column within tile

    // ---- prefetch mask row for my sort row (warps 0-3) ----------------------
    int4 m4p[4];
    if (warp < 4) {
        const int4* Mrow = (const int4*)(mask + (i0 + warp) * B);
#pragma unroll
        for (int qq = 0; qq < 4; qq++) m4p[qq] = Mrow[lane * 4 + qq];
    }

    // ---- stage u = f(anchor rows) + eps --------------------------------------
    if (tid < 4 * DIM) {
        const int r = tid >> 7, d = tid & 127;
        u_s[r * LDJ + d] = F[(i0 + r) * DIM + d] + EPSF;
    }
    __syncthreads();

    // ---- |u_i|^2 (warps 0-3; warp w -> row w) --------------------------------
    if (warp < 4) {
        float s = 0.f;
#pragma unroll
        for (int qq = 0; qq < 4; qq++) {
            const float x = u_s[warp * LDJ + lane + 32 * qq];
            s = fmaf(x, x, s);
        }
#pragma unroll
        for (int off = 16; off; off >>= 1) s += __shfl_down_sync(FULLM, s, off);
        if (lane == 0) s_ni[warp] = s;
    }

    const float4* F4 = (const float4*)F;
    const float4* U0 = (const float4*)&u_s[0 * LDJ + 32 * q];
    const float4* U1 = (const float4*)&u_s[1 * LDJ + 32 * q];
    const float4* U2 = (const float4*)&u_s[2 * LDJ + 32 * q];
    const float4* U3 = (const float4*)&u_s[3 * LDJ + 32 * q];

    // ---- Phase A: 2 j-tiles of 256 -------------------------------------------
#pragma unroll
    for (int p = 0; p < 2; p++) {
        __syncthreads();   // protect Fj_s + partials reuse across tiles
        // stage tile rows [256p, 256p+256): coalesced LDG.128 -> STS.128
#pragma unroll
        for (int k = 0; k < 8; k++) {
            const int idx = tid + (k << 10);
            const int r = idx >> 5, c = idx & 31;
            const float4 fv = F4[(TJ * p + r) * 32 + c];
            *(float4*)&Fj_s[r * LDJ + 4 * c] = fv;
        }
        __syncthreads();

        float a0 = 0.f, a1 = 0.f, a2 = 0.f, a3 = 0.f, nf = 0.f;
        const float4* fj = (const float4*)&Fj_s[jl * LDJ + 32 * q];
#pragma unroll
        for (int dq = 0; dq < 8; dq++) {
            const float4 fv = fj[dq];
            nf = fmaf(fv.x, fv.x, fmaf(fv.y, fv.y,
                 fmaf(fv.z, fv.z, fmaf(fv.w, fv.w, nf))));
            const float4 ua = U0[dq];
            a0 = fmaf(ua.x, fv.x, fmaf(ua.y, fv.y,
                 fmaf(ua.z, fv.z, fmaf(ua.w, fv.w, a0))));
            const float4 ub = U1[dq];
            a1 = fmaf(ub.x, fv.x, fmaf(ub.y, fv.y,
                 fmaf(ub.z, fv.z, fmaf(ub.w, fv.w, a1))));
            const float4 uc = U2[dq];
            a2 = fmaf(uc.x, fv.x, fmaf(uc.y, fv.y,
                 fmaf(uc.z, fv.z, fmaf(uc.w, fv.w, a2))));
            const float4 ud = U3[dq];
            a3 = fmaf(ud.x, fv.x, fmaf(ud.y, fv.y,
                 fmaf(ud.z, fv.z, fmaf(ud.w, fv.w, a3))));
        }

        // combine quarters: q=1..3 publish; q=0 finishes + writes D
        if (q != 0) {
            s_p4[(q - 1) * 256 + jl] = make_float4(a0, a1, a2, a3);
            s_pn[(q - 1) * 256 + jl] = nf;
        }
        __syncthreads();
        if (q == 0) {
            const float4 p1 = s_p4[jl], p2 = s_p4[256 + jl], p3 = s_p4[512 + jl];
            const float NF = nf + s_pn[jl] + s_pn[256 + jl] + s_pn[512 + jl];
            const float A0 = a0 + p1.x + p2.x + p3.x;
            const float A1 = a1 + p1.y + p2.y + p3.y;
            const float A2 = a2 + p1.z + p2.z + p3.z;
            const float A3 = a3 + p1.w + p2.w + p3.w;
            const int jc = p * TJ + jl;
            D_s[0 * LDD + jc] = sqrtf(fmaxf(s_ni[0] + NF - 2.f * A0, 0.f));
            D_s[1 * LDD + jc] = sqrtf(fmaxf(s_ni[1] + NF - 2.f * A1, 0.f));
            D_s[2 * LDD + jc] = sqrtf(fmaxf(s_ni[2] + NF - 2.f * A2, 0.f));
            D_s[3 * LDD + jc] = sqrtf(fmaxf(s_ni[3] + NF - 2.f * A3, 0.f));
        }
    }
    __syncthreads();   // D_s complete

    // =========================================================================
    // Phase B (warps 0-3): register-resident sort of row i0+warp.
    // Element e = lane*16 + r. LSB tag: pos=(d+margin)|1, neg=d&~1,
    // excluded diagonal = BIGF (value-guarded out of float sums).
    // =========================================================================
    if (warp < 4) {
        const int i = i0 + warp;
        float v[16];
        int npos = 0, nneg = 0;

#pragma unroll
        for (int qq = 0; qq < 4; qq++) {
            const float4 d4 = *(const float4*)&D_s[warp * LDD + lane * 16 + 4 * qq];
            const float dv[4] = {d4.x, d4.y, d4.z, d4.w};
            const int   mv[4] = {m4p[qq].x, m4p[qq].y, m4p[qq].z, m4p[qq].w};
#pragma unroll
            for (int t = 0; t < 4; t++) {
                const int j = lane * 16 + qq * 4 + t;
                unsigned kb;
                if (mv[t] != 0) {
                    kb = __float_as_uint(dv[t] + MARGIN) | 1u;
                    npos++;
                } else if (j == i) {
                    kb = __float_as_uint(BIGF) & ~1u;
                } else {
                    kb = __float_as_uint(dv[t]) & ~1u;
                    nneg++;
                }
                v[qq * 4 + t] = __uint_as_float(kb);
            }
        }
        const int np = __reduce_add_sync(FULLM, npos);
        const int nn = __reduce_add_sync(FULLM, nneg);

        // bitonic sort of 512 keys, ascending (register + shfl only)
#pragma unroll
        for (int k = 2; k <= 512; k <<= 1) {
            const bool asc_lane_valid = (k >= 16);
            const bool asc_l = ((lane & (k >> 4)) == 0);
#pragma unroll
            for (int j = k >> 1; j >= 1; j >>= 1) {
                if (j >= 16) {
                    const int jl2 = j >> 4;
                    const bool keep_min = (((lane & jl2) == 0) == asc_l);
#pragma unroll
                    for (int r = 0; r < 16; r++) {
                        const float pv = __shfl_xor_sync(FULLM, v[r], jl2);
                        v[r] = keep_min ? fminf(v[r], pv) : fmaxf(v[r], pv);
                    }
                } else {
#pragma unroll
                    for (int r = 0; r < 16; r++) {
                        if ((r & j) == 0) {
                            const int r2 = r | j;
                            const bool asc = asc_lane_valid ? asc_l : ((r & k) == 0);
                            const float a = v[r], bb = v[r2];
                            const float lo = fminf(a, bb), hi = fmaxf(a, bb);
                            v[r]  = asc ? lo : hi;
                            v[r2] = asc ? hi : lo;
                        }
                    }
                }
            }
        }

        // pass 1: per-lane negative (sum, count), sentinel value-guarded
        float runs = 0.f;
        int   runc = 0;
#pragma unroll
        for (int r = 0; r < 16; r++) {
            const bool isneg = ((__float_as_uint(v[r]) & 1u) == 0) && (v[r] < SENTTH);
            if (isneg) { runs += v[r]; runc++; }
        }
        float ls = runs;
        int   lc = runc;
#pragma unroll
        for (int off = 1; off < 32; off <<= 1) {
            const float y = __shfl_up_sync(FULLM, ls, off);
            const int   z = __shfl_up_sync(FULLM, lc, off);
            if (lane >= off) { ls += y; lc += z; }
        }
        float rs = ls - runs;
        int   rc = lc - runc;

        // pass 2: positive contributions
        float local = 0.f;
#pragma unroll
        for (int r = 0; r < 16; r++) {
            const bool ispos = (__float_as_uint(v[r]) & 1u) != 0;
            if (ispos) {
                local += (float)rc * v[r] - rs;
            } else if (v[r] < SENTTH) {
                rs += v[r];
                rc++;
            }
        }

#pragma unroll
        for (int off = 16; off; off >>= 1)
            local += __shfl_down_sync(FULLM, local, off);

        if (lane == 0) {
            s_bs[warp] = local;
            s_bd[warp] = (unsigned long long)np * (unsigned long long)nn;
        }
    }
    __syncthreads();

    if (tid == 0) {
        const float s = s_bs[0] + s_bs[1] + s_bs[2] + s_bs[3];
        const unsigned long long d = s_bd[0] + s_bd[1] + s_bd[2] + s_bd[3];
        atomicAdd(&g_num, (double)s);
        atomicAdd(&g_den, d);
        __threadfence();
        const unsigned int ticket = atomicAdd(&g_done, 1u);
        if (ticket == gridDim.x - 1) {
            const double num = atomicAdd(&g_num, 0.0);
            const unsigned long long den = atomicAdd(&g_den, 0ull);
            out[0] = (den > 0ull) ? (float)(num / (double)den) : 0.0f;
            g_num  = 0.0;
            g_den  = 0ull;
            __threadfence();
            g_done = 0u;
        }
    }
}

// ---------------------------------------------------------------------------
extern "C" void kernel_launch(void* const* d_in, const int* in_sizes, int n_in,
                              void* d_out, int out_size) {
    const float* features = (const float*)d_in[0];   // [512,128] f32
    const int*   mask     = (const int*)d_in[1];     // [512,512] i32
    float* out = (float*)d_out;

    const int smem_bytes =
        (4 * LDJ + TJ * LDJ + 4 * LDD + 4 + 3 * 256 * 4 + 3 * 256 + 4)
            * (int)sizeof(float)
        + 4 * (int)sizeof(unsigned long long);
    static bool attr_set = false;
    if (!attr_set) {
        cudaFuncSetAttribute(fused_kernel, cudaFuncAttributeMaxDynamicSharedMemorySize,
                             smem_bytes);
        attr_set = true;
    }

    fused_kernel<<<B / 4, NT, smem_bytes>>>(features, mask, out);
}

// round 12
// speedup vs baseline: 1.1345x; 1.1174x over previous
#include <cuda_runtime.h>
#include <cuda_bf16.h>
#include <cstdint>

#define B      512
#define DIM    128
#define MARGIN 0.2f
#define EPSF   1e-6f
#define BIGF   1e30f
#define SENTTH 1e29f
#define FULLM  0xffffffffu

#define LDJ 132   // Fj/u row stride (floats); quarter-warp conflict-free LDS.128
#define LDD 516   // D slab row stride (floats)
#define TJ  256   // j-tile size (2 tiles cover B=512)
#define NT  512   // threads per block (R9 shape — best measured)

// Accumulators (allocation-free rule). Statics init to zero; the last block
// resets them after use, so every graph replay starts from zero.
__device__ double g_num = 0.0;
__device__ unsigned long long g_den = 0ull;
__device__ unsigned int g_done = 0u;

static __device__ __forceinline__ unsigned smem_u32(const void* p) {
    return (unsigned)__cvta_generic_to_shared(p);
}

// packed f32x2 FMA: acc = a*b + acc   (2 FMAs / instruction; PTX-only form)
#define FMA2(acc, a, b) \
    asm volatile("fma.rn.f32x2 %0, %1, %2, %0;" : "+l"(acc) : "l"(a), "l"(b))

// 16B shared load as two packed f32x2 operands
#define LDS_V2B64(lo, hi, addr) \
    asm volatile("ld.shared.v2.b64 {%0, %1}, [%2];" : "=l"(lo), "=l"(hi) : "r"(addr))

static __device__ __forceinline__ float hadd_f32x2(uint64_t p) {
    float lo, hi;
    asm volatile("mov.b64 {%0, %1}, %2;" : "=f"(lo), "=f"(hi) : "l"(p));
    return lo + hi;
}

// ---------------------------------------------------------------------------
// ONE fused kernel, 512 threads (R9 structure + f32x2 inner loop).
// Block b = anchor rows [4b, 4b+4).
// Phase A: 4x512 distance slab via norm expansion; thread (q = tid/128,
//   jl = tid%128... no: q = tid>>7? (R9: q = tid>>7 was 128-col tiles) —
//   here as R9: q = tid>>7 over 4 quarters? R9 used q=tid>>7 with TJ=256?
//   R9 mapping: q = tid >> 8 (binary half)? — actual mapping below:
//   q = tid / 128 gives 4 quarters of 32 dims, jl = tid % 128 would give 128
//   columns; R9 used (h = tid>>8, jl = tid&255) with halves. We keep R9's
//   PROVEN mapping: quarter q = tid >> 7 is wrong for NT=512; correct R9
//   mapping is h-split. See code: q = tid >> 7 → 4 groups of 128 columns?
//   -- Implemented below exactly as R9: q = tid >> 7 over d-quarters of 32
//   dims with jl = tid & 127 and 4 j-tiles? No — R9 had 2 tiles of 256 with
//   h = tid >> 8. THIS kernel uses R9's exact geometry: h = tid >> 8 (two
//   d-halves of 64 dims), jl = tid & 255, 2 j-tiles of 256.
// Phase B (warps 0-3): register-resident bitonic sort (verified R6).
// ---------------------------------------------------------------------------
__global__ __launch_bounds__(NT) void fused_kernel(const float* __restrict__ F,
                                                   const int* __restrict__ mask,
                                                   float* __restrict__ out) {
    extern __shared__ float sm[];
    float*  u_s    = sm;                        //   4 * 132
    float*  Fj_s   = u_s + 4 * LDJ;             // 256 * 132
    float*  D_s    = Fj_s + TJ * LDJ;           //   4 * 516
    float*  s_ni   = D_s + 4 * LDD;             //   4
    float*  s_part = s_ni + 4;                  // 256 * 6 (h=1 partials)
    float*  s_bs   = s_part + 256 * 6;          //   4
    unsigned long long* s_bd = (unsigned long long*)(s_bs + 4);   // 4

    const int tid  = threadIdx.x;
    const int lane = tid & 31;
    const int warp = tid >> 5;
    const int i0   = blockIdx.x * 4;
    const int h    = tid >> 8;        // d-half owner (uniform per warp)
    const int jl   = tid & 255;       // j column within tile

    // ---- prefetch mask row for my sort row (warps 0-3) ----------------------
    int4 m4p[4];
    if (warp < 4) {
        const int4* Mrow = (const int4*)(mask + (i0 + warp) * B);
#pragma unroll
        for (int qq = 0; qq < 4; qq++) m4p[qq] = Mrow[lane * 4 + qq];
    }

    // ---- stage u = f(anchor rows) + eps --------------------------------------
    for (int idx = tid; idx < 4 * DIM; idx += NT) {
        const int r = idx >> 7, d = idx & 127;
        u_s[r * LDJ + d] = F[(i0 + r) * DIM + d] + EPSF;
    }
    __syncthreads();

    // ---- |u_i|^2 (warps 0-3; warp w -> row w) --------------------------------
    if (warp < 4) {
        float s = 0.f;
#pragma unroll
        for (int qq = 0; qq < 4; qq++) {
            const float x = u_s[warp * LDJ + lane + 32 * qq];
            s = fmaf(x, x, s);
        }
#pragma unroll
        for (int off = 16; off; off >>= 1) s += __shfl_down_sync(FULLM, s, off);
        if (lane == 0) s_ni[warp] = s;
    }

    const float4* F4 = (const float4*)F;
    // shared-space base addresses for my d-half (64 dims = 16 float4)
    const unsigned u0a = smem_u32(&u_s[0 * LDJ + 64 * h]);
    const unsigned u1a = smem_u32(&u_s[1 * LDJ + 64 * h]);
    const unsigned u2a = smem_u32(&u_s[2 * LDJ + 64 * h]);
    const unsigned u3a = smem_u32(&u_s[3 * LDJ + 64 * h]);
    const unsigned fja = smem_u32(&Fj_s[jl * LDJ + 64 * h]);

    // ---- Phase A: 2 j-tiles of 256 (f32x2 packed inner loop) -----------------
#pragma unroll
    for (int p = 0; p < 2; p++) {
        __syncthreads();   // protect Fj_s + s_part reuse across tiles
        // stage tile rows [256p, 256p+256): coalesced LDG.128 -> STS.128
#pragma unroll
        for (int k = 0; k < 16; k++) {
            const int idx = tid + (k << 9);
            const int r = idx >> 5, c = idx & 31;
            const float4 fv = F4[(TJ * p + r) * 32 + c];
            *(float4*)&Fj_s[r * LDJ + 4 * c] = fv;
        }
        __syncthreads();

        uint64_t A0 = 0ull, A1 = 0ull, A2 = 0ull, A3 = 0ull, NF2 = 0ull;
#pragma unroll
        for (int dq = 0; dq < 16; dq++) {
            uint64_t f0, f1, x0, x1;
            LDS_V2B64(f0, f1, fja + 16 * dq);
            FMA2(NF2, f0, f0);
            FMA2(NF2, f1, f1);
            LDS_V2B64(x0, x1, u0a + 16 * dq);
            FMA2(A0, x0, f0);
            FMA2(A0, x1, f1);
            LDS_V2B64(x0, x1, u1a + 16 * dq);
            FMA2(A1, x0, f0);
            FMA2(A1, x1, f1);
            LDS_V2B64(x0, x1, u2a + 16 * dq);
            FMA2(A2, x0, f0);
            FMA2(A2, x1, f1);
            LDS_V2B64(x0, x1, u3a + 16 * dq);
            FMA2(A3, x0, f0);
            FMA2(A3, x1, f1);
        }
        const float a0 = hadd_f32x2(A0);
        const float a1 = hadd_f32x2(A1);
        const float a2 = hadd_f32x2(A2);
        const float a3 = hadd_f32x2(A3);
        const float nf = hadd_f32x2(NF2);

        // combine halves: h=1 publishes partials; h=0 finishes + writes D
        if (h == 1) {
            float* dst = &s_part[jl * 6];
            dst[0] = a0; dst[1] = a1; dst[2] = a2; dst[3] = a3; dst[4] = nf;
        }
        __syncthreads();
        if (h == 0) {
            const float* src = &s_part[jl * 6];
            const float B0 = a0 + src[0];
            const float B1 = a1 + src[1];
            const float B2 = a2 + src[2];
            const float B3 = a3 + src[3];
            const float NF = nf + src[4];
            const int jc = p * TJ + jl;
            D_s[0 * LDD + jc] = sqrtf(fmaxf(s_ni[0] + NF - 2.f * B0, 0.f));
            D_s[1 * LDD + jc] = sqrtf(fmaxf(s_ni[1] + NF - 2.f * B1, 0.f));
            D_s[2 * LDD + jc] = sqrtf(fmaxf(s_ni[2] + NF - 2.f * B2, 0.f));
            D_s[3 * LDD + jc] = sqrtf(fmaxf(s_ni[3] + NF - 2.f * B3, 0.f));
        }
    }
    __syncthreads();   // D_s complete

    // =========================================================================
    // Phase B (warps 0-3): register-resident sort of row i0+warp (R6-verified).
    // Element e = lane*16 + r. LSB tag: pos=(d+margin)|1, neg=d&~1,
    // excluded diagonal = BIGF (value-guarded out of float sums).
    // =========================================================================
    if (warp < 4) {
        const int i = i0 + warp;
        float v[16];
        int npos = 0, nneg = 0;

#pragma unroll
        for (int qq = 0; qq < 4; qq++) {
            const float4 d4 = *(const float4*)&D_s[warp * LDD + lane * 16 + 4 * qq];
            const float dv[4] = {d4.x, d4.y, d4.z, d4.w};
            const int   mv[4] = {m4p[qq].x, m4p[qq].y, m4p[qq].z, m4p[qq].w};
#pragma unroll
            for (int t = 0; t < 4; t++) {
                const int j = lane * 16 + qq * 4 + t;
                unsigned kb;
                if (mv[t] != 0) {
                    kb = __float_as_uint(dv[t] + MARGIN) | 1u;
                    npos++;
                } else if (j == i) {
                    kb = __float_as_uint(BIGF) & ~1u;
                } else {
                    kb = __float_as_uint(dv[t]) & ~1u;
                    nneg++;
                }
                v[qq * 4 + t] = __uint_as_float(kb);
            }
        }
        const int np = __reduce_add_sync(FULLM, npos);
        const int nn = __reduce_add_sync(FULLM, nneg);

        // bitonic sort of 512 keys, ascending (register + shfl only)
#pragma unroll
        for (int k = 2; k <= 512; k <<= 1) {
            const bool asc_lane_valid = (k >= 16);
            const bool asc_l = ((lane & (k >> 4)) == 0);
#pragma unroll
            for (int j = k >> 1; j >= 1; j >>= 1) {
                if (j >= 16) {
                    const int jl2 = j >> 4;
                    const bool keep_min = (((lane & jl2) == 0) == asc_l);
#pragma unroll
                    for (int r = 0; r < 16; r++) {
                        const float pv = __shfl_xor_sync(FULLM, v[r], jl2);
                        v[r] = keep_min ? fminf(v[r], pv) : fmaxf(v[r], pv);
                    }
                } else {
#pragma unroll
                    for (int r = 0; r < 16; r++) {
                        if ((r & j) == 0) {
                            const int r2 = r | j;
                            const bool asc = asc_lane_valid ? asc_l : ((r & k) == 0);
                            const float a = v[r], bb = v[r2];
                            const float lo = fminf(a, bb), hi = fmaxf(a, bb);
                            v[r]  = asc ? lo : hi;
                            v[r2] = asc ? hi : lo;
                        }
                    }
                }
            }
        }

        // pass 1: per-lane negative (sum, count), sentinel value-guarded
        float runs = 0.f;
        int   runc = 0;
#pragma unroll
        for (int r = 0; r < 16; r++) {
            const bool isneg = ((__float_as_uint(v[r]) & 1u) == 0) && (v[r] < SENTTH);
            if (isneg) { runs += v[r]; runc++; }
        }
        float ls = runs;
        int   lc = runc;
#pragma unroll
        for (int off = 1; off < 32; off <<= 1) {
            const float y = __shfl_up_sync(FULLM, ls, off);
            const int   z = __shfl_up_sync(FULLM, lc, off);
            if (lane >= off) { ls += y; lc += z; }
        }
        float rs = ls - runs;
        int   rc = lc - runc;

        // pass 2: positive contributions
        float local = 0.f;
#pragma unroll
        for (int r = 0; r < 16; r++) {
            const bool ispos = (__float_as_uint(v[r]) & 1u) != 0;
            if (ispos) {
                local += (float)rc * v[r] - rs;
            } else if (v[r] < SENTTH) {
                rs += v[r];
                rc++;
            }
        }

#pragma unroll
        for (int off = 16; off; off >>= 1)
            local += __shfl_down_sync(FULLM, local, off);

        if (lane == 0) {
            s_bs[warp] = local;
            s_bd[warp] = (unsigned long long)np * (unsigned long long)nn;
        }
    }
    __syncthreads();

    if (tid == 0) {
        const float s = s_bs[0] + s_bs[1] + s_bs[2] + s_bs[3];
        const unsigned long long d = s_bd[0] + s_bd[1] + s_bd[2] + s_bd[3];
        atomicAdd(&g_num, (double)s);
        atomicAdd(&g_den, d);
        __threadfence();
        const unsigned int ticket = atomicAdd(&g_done, 1u);
        if (ticket == gridDim.x - 1) {
            const double num = atomicAdd(&g_num, 0.0);
            const unsigned long long den = atomicAdd(&g_den, 0ull);
            out[0] = (den > 0ull) ? (float)(num / (double)den) : 0.0f;
            g_num  = 0.0;
            g_den  = 0ull;
            __threadfence();
            g_done = 0u;
        }
    }
}

// ---------------------------------------------------------------------------
extern "C" void kernel_launch(void* const* d_in, const int* in_sizes, int n_in,
                              void* d_out, int out_size) {
    const float* features = (const float*)d_in[0];   // [512,128] f32
    const int*   mask     = (const int*)d_in[1];     // [512,512] i32
    float* out = (float*)d_out;

    const int smem_bytes =
        (4 * LDJ + TJ * LDJ + 4 * LDD + 4 + 256 * 6 + 4) * (int)sizeof(float)
        + 4 * (int)sizeof(unsigned long long);
    static bool attr_set = false;
    if (!attr_set) {
        cudaFuncSetAttribute(fused_kernel, cudaFuncAttributeMaxDynamicSharedMemorySize,
                             smem_bytes);
        attr_set = true;
    }

    fused_kernel<<<B / 4, NT, smem_bytes>>>(features, mask, out);
}